// round 8
// baseline (speedup 1.0000x reference)
#include <cuda_runtime.h>
#include <cuda_bf16.h>
#include <cstdint>

// GMMVAE ELBO. log_px via decomposition: sum(x-mean)^2 = sum x'^2 - 2 z.G + z M z
// with G = x' @ W^T (bf16 mma, x streamed coalesced), M = W W^T (exact fp32).
typedef unsigned long long ull;

#define B_TOT 16384
#define XD 784
#define ZD 64
#define KK 64
#define ROWS 128
#define THREADS 512
#define NBLK (B_TOT / ROWS)   // 128
#define CHUNKS 13             // 13*64 = 832 padded x-cols
#define RSTR 66
#define LOG2PI 1.8378770664093453
#define FIXSCALE 262144.0

__device__ float g_s2T[ZD * KK];
__device__ float g_na2T[ZD * KK];
__device__ float g_cc2[KK];
__device__ float g_ck2[KK];
__device__ float g_M[ZD * ZD];     // W W^T, fp32 exact
__device__ ull g_acc;
__device__ unsigned g_cnt;
__device__ __align__(16) __nv_bfloat16 g_Wt[XD * 64];  // [c][z] 128B swizzled rows

// ---- smem byte offsets ----
#define OFF_RED   0
#define OFF_BIAS  128      // 3136 -> 3264
#define OFF_M     3264     // 16384 -> 19648
#define OFF_WTB   19712    // 832*128 = 106496 -> 126208
#define OFF_XB    126208   // 2*16384 -> 158976
// overlays (pool 19712..158976) after GEMM:
#define OFF_ZR    19712    // 33792
#define OFF_V1    53504
#define OFF_QM    87296
#define OFF_S2T   121088   // 16384
#define OFF_NA2T  137472   // -> 153856
#define OFF_COMP  158976   // 32768
#define OFF_KLZ   191744   // -> 224512
#define SMEM_BYTES 224512

__device__ __forceinline__ uint32_t smem_u32(const void* p) {
    uint32_t a;
    asm("{ .reg .u64 t; cvta.to.shared.u64 t, %1; cvt.u32.u64 %0, t; }" : "=r"(a) : "l"(p));
    return a;
}
__device__ __forceinline__ ull fma2o(ull a, ull b, ull c) {
    ull d;
    asm("fma.rn.f32x2 %0, %1, %2, %3;" : "=l"(d) : "l"(a), "l"(b), "l"(c));
    return d;
}
__device__ __forceinline__ ull dup2(float x) {
    ull r;
    asm("mov.b64 %0, {%1, %1};" : "=l"(r) : "f"(x));
    return r;
}
__device__ __forceinline__ void unpack2(ull v, float& lo, float& hi) {
    asm("mov.b64 {%0, %1}, %2;" : "=f"(lo), "=f"(hi) : "l"(v));
}
__device__ __forceinline__ void ldm_x4(uint32_t& r0, uint32_t& r1, uint32_t& r2,
                                       uint32_t& r3, uint32_t addr) {
    asm volatile("ldmatrix.sync.aligned.m8n8.x4.shared.b16 {%0,%1,%2,%3}, [%4];"
                 : "=r"(r0), "=r"(r1), "=r"(r2), "=r"(r3) : "r"(addr));
}
__device__ __forceinline__ void mma_bf16(float& c0, float& c1, float& c2, float& c3,
                                         uint32_t a0, uint32_t a1, uint32_t a2, uint32_t a3,
                                         uint32_t b0, uint32_t b1) {
    asm volatile("mma.sync.aligned.m16n8k16.row.col.f32.bf16.bf16.f32 "
                 "{%0,%1,%2,%3}, {%4,%5,%6,%7}, {%8,%9}, {%0,%1,%2,%3};"
                 : "+f"(c0), "+f"(c1), "+f"(c2), "+f"(c3)
                 : "r"(a0), "r"(a1), "r"(a2), "r"(a3), "r"(b0), "r"(b1));
}
__device__ __forceinline__ uint32_t swz(int r, int zp) {
    return (uint32_t)(r * 128 + (((zp >> 2) ^ (r & 7)) << 4) + 4 * (zp & 3));
}

// ======================= prep kernel (grid 31) =======================
// 0..13: W transpose -> g_Wt [c][z] bf16 swizzled; 14: per-k consts + acc reset;
// 15..30: M = W W^T (4 i-rows per block, fp32 exact)
__global__ void prep_kernel(const float* __restrict__ W,
                            const float* __restrict__ pmu,
                            const float* __restrict__ pls) {
    const int b = blockIdx.x, tid = threadIdx.x;
    if (b < 14) {
        __shared__ float sc[64 * 57];
        const int c0 = b * 56;
        for (int i = tid; i < 64 * 56; i += 256) {
            const int z = i / 56, c = i - z * 56;
            sc[z * 57 + c] = W[z * XD + c0 + c];
        }
        __syncthreads();
        for (int i = tid; i < 56 * 32; i += 256) {
            const int c = i >> 5, zp = i & 31;
            __nv_bfloat162 bv = __floats2bfloat162_rn(sc[(2 * zp) * 57 + c],
                                                      sc[(2 * zp + 1) * 57 + c]);
            *(uint32_t*)((char*)g_Wt + swz(c0 + c, zp)) = *(uint32_t*)&bv;
        }
    } else if (b == 14) {
        const int k = tid >> 2, q = tid & 3;
        float lsum = 0.f, c1 = 0.f;
#pragma unroll
        for (int i = 0; i < 16; i++) {
            const int z = 16 * q + i;
            float ls = pls[k * ZD + z];
            float mu = pmu[k * ZD + z];
            float s2i = expf(-2.f * ls);
            g_s2T[z * KK + k] = s2i;
            g_na2T[z * KK + k] = -2.f * mu * s2i;
            lsum += ls;
            c1 = fmaf(mu * mu, s2i, c1);
        }
#pragma unroll
        for (int o = 1; o < 4; o <<= 1) {
            lsum += __shfl_xor_sync(~0u, lsum, o);
            c1 += __shfl_xor_sync(~0u, c1, o);
        }
        if (q == 0) {
            g_cc2[k] = (float)(-(double)lsum - 32.0 * LOG2PI - 0.5 * (double)c1);
            g_ck2[k] = lsum + 0.5f * c1;
        }
        if (tid == 0) { g_acc = 0ull; g_cnt = 0u; }
    } else {
        const int bi = b - 15;          // 0..15 -> i rows 4bi..4bi+3
        __shared__ float Wi[4 * XD];
        for (int i = tid; i < 4 * XD; i += 256) {
            const int r = i / XD, c = i - r * XD;
            Wi[i] = W[(4 * bi + r) * XD + c];
        }
        __syncthreads();
        const int j = tid >> 2, q = tid & 3;
        float s0 = 0.f, s1 = 0.f, s2 = 0.f, s3 = 0.f;
        const float* wj = W + j * XD + q * 196;
        for (int c = 0; c < 196; c++) {
            const float wv = wj[c];
            const int cc = q * 196 + c;
            s0 = fmaf(Wi[cc], wv, s0);
            s1 = fmaf(Wi[XD + cc], wv, s1);
            s2 = fmaf(Wi[2 * XD + cc], wv, s2);
            s3 = fmaf(Wi[3 * XD + cc], wv, s3);
        }
#pragma unroll
        for (int o = 1; o < 4; o <<= 1) {
            s0 += __shfl_xor_sync(~0u, s0, o);
            s1 += __shfl_xor_sync(~0u, s1, o);
            s2 += __shfl_xor_sync(~0u, s2, o);
            s3 += __shfl_xor_sync(~0u, s3, o);
        }
        if (q == 0) {
            g_M[(4 * bi + 0) * ZD + j] = s0;
            g_M[(4 * bi + 1) * ZD + j] = s1;
            g_M[(4 * bi + 2) * ZD + j] = s2;
            g_M[(4 * bi + 3) * ZD + j] = s3;
        }
    }
}

// ======================= main kernel =======================
extern __shared__ char smem[];

__global__ __launch_bounds__(THREADS, 1)
void main_kernel(const float* __restrict__ x, const float* __restrict__ pi,
                 const float* __restrict__ qmu, const float* __restrict__ qls,
                 const float* __restrict__ eps, const float* __restrict__ bdec,
                 float* __restrict__ out) {
    const int tid = threadIdx.x;
    const int wid = tid >> 5, lane = tid & 31;
    const int rowbase = blockIdx.x * ROWS;
    const uint32_t sbase = smem_u32(smem);
    float* red = (float*)(smem + OFF_RED);
    float* biasS = (float*)(smem + OFF_BIAS);

    // ---- x-pipe thread mapping ----
    const int xr = tid >> 2, xcg = tid & 3;
    const float* xcol = x + (size_t)(rowbase + xr) * XD + 16 * xcg;
    float4 f0, f1, f2, f3;
    bool xv = false;
    float sx0 = 0.f, sx1 = 0.f;

#define XLDG(ch) do {                                                          \
    xv = (64 * (ch) + 16 * xcg) < XD;                                          \
    if (xv) {                                                                  \
        const float4* p_ = (const float4*)(xcol + 64 * (ch));                  \
        f0 = p_[0]; f1 = p_[1]; f2 = p_[2]; f3 = p_[3];                        \
    } else {                                                                   \
        f0 = f1 = f2 = f3 = make_float4(0.f, 0.f, 0.f, 0.f);                   \
    }                                                                          \
} while (0)

#define XPROC(ch, buf) do {                                                    \
    if (xv) {                                                                  \
        const float4* bp_ = (const float4*)(biasS + 64 * (ch) + 16 * xcg);     \
        float4 b0_ = bp_[0], b1_ = bp_[1], b2_ = bp_[2], b3_ = bp_[3];         \
        f0.x -= b0_.x; f0.y -= b0_.y; f0.z -= b0_.z; f0.w -= b0_.w;            \
        f1.x -= b1_.x; f1.y -= b1_.y; f1.z -= b1_.z; f1.w -= b1_.w;            \
        f2.x -= b2_.x; f2.y -= b2_.y; f2.z -= b2_.z; f2.w -= b2_.w;            \
        f3.x -= b3_.x; f3.y -= b3_.y; f3.z -= b3_.z; f3.w -= b3_.w;            \
        sx0 = fmaf(f0.x, f0.x, sx0); sx1 = fmaf(f0.y, f0.y, sx1);              \
        sx0 = fmaf(f0.z, f0.z, sx0); sx1 = fmaf(f0.w, f0.w, sx1);              \
        sx0 = fmaf(f1.x, f1.x, sx0); sx1 = fmaf(f1.y, f1.y, sx1);              \
        sx0 = fmaf(f1.z, f1.z, sx0); sx1 = fmaf(f1.w, f1.w, sx1);              \
        sx0 = fmaf(f2.x, f2.x, sx0); sx1 = fmaf(f2.y, f2.y, sx1);              \
        sx0 = fmaf(f2.z, f2.z, sx0); sx1 = fmaf(f2.w, f2.w, sx1);              \
        sx0 = fmaf(f3.x, f3.x, sx0); sx1 = fmaf(f3.y, f3.y, sx1);              \
        sx0 = fmaf(f3.z, f3.z, sx0); sx1 = fmaf(f3.w, f3.w, sx1);              \
    }                                                                          \
    __nv_bfloat162 v0_ = __floats2bfloat162_rn(f0.x, f0.y);                    \
    __nv_bfloat162 v1_ = __floats2bfloat162_rn(f0.z, f0.w);                    \
    __nv_bfloat162 v2_ = __floats2bfloat162_rn(f1.x, f1.y);                    \
    __nv_bfloat162 v3_ = __floats2bfloat162_rn(f1.z, f1.w);                    \
    __nv_bfloat162 v4_ = __floats2bfloat162_rn(f2.x, f2.y);                    \
    __nv_bfloat162 v5_ = __floats2bfloat162_rn(f2.z, f2.w);                    \
    __nv_bfloat162 v6_ = __floats2bfloat162_rn(f3.x, f3.y);                    \
    __nv_bfloat162 v7_ = __floats2bfloat162_rn(f3.z, f3.w);                    \
    char* xb_ = smem + OFF_XB + (buf) * 16384 + xr * 128;                      \
    *(uint4*)(xb_ + (((2 * xcg) ^ (xr & 7)) << 4)) =                           \
        make_uint4(*(uint32_t*)&v0_, *(uint32_t*)&v1_,                         \
                   *(uint32_t*)&v2_, *(uint32_t*)&v3_);                        \
    *(uint4*)(xb_ + (((2 * xcg + 1) ^ (xr & 7)) << 4)) =                       \
        make_uint4(*(uint32_t*)&v4_, *(uint32_t*)&v5_,                         \
                   *(uint32_t*)&v6_, *(uint32_t*)&v7_);                        \
} while (0)

    XLDG(0);
    // ---- init copies (overlap with x LDG latency) ----
    {
        const uint4* src = (const uint4*)g_Wt;
        uint4* dst = (uint4*)(smem + OFF_WTB);
        for (int i = tid; i < (XD * 128) / 16; i += THREADS) dst[i] = src[i];
        uint4* ztail = (uint4*)(smem + OFF_WTB + XD * 128);
        for (int i = tid; i < ((832 - XD) * 128) / 16; i += THREADS)
            ztail[i] = make_uint4(0, 0, 0, 0);
        const uint4* ms = (const uint4*)g_M;
        uint4* md = (uint4*)(smem + OFF_M);
        for (int i = tid; i < (ZD * ZD) / 4; i += THREADS) md[i] = ms[i];
    }
    for (int i = tid; i < XD; i += THREADS) biasS[i] = bdec[i];
    __syncthreads();
    XPROC(0, 0);
    XLDG(1);
    __syncthreads();

    // ================= Stage 1: G = x' @ W^T, fragments in regs ==============
    const int g = lane >> 3, lr = lane & 7;
    const int mrow = 16 * (wid & 7), nh = wid >> 3;
    const int ra = mrow + lr + 8 * (g & 1);
    const int gx = g >> 1;
    const uint32_t aBase0 = sbase + OFF_XB + ra * 128;
    const uint32_t bRow = (8 * (g & 1) + lr) * 128;
    const uint32_t bBase0 = sbase + OFF_WTB + bRow + ((((4 * nh) + gx) ^ lr) << 4);
    const uint32_t bBase1 = sbase + OFF_WTB + bRow + ((((4 * nh) + 2 + gx) ^ lr) << 4);

    float acc[4][4];
#pragma unroll
    for (int nt = 0; nt < 4; nt++)
#pragma unroll
        for (int i = 0; i < 4; i++) acc[nt][i] = 0.f;

    for (int ch = 0; ch < CHUNKS; ch++) {
        const uint32_t aB = aBase0 + (ch & 1) * 16384;
        uint32_t a[16];
#pragma unroll
        for (int kt = 0; kt < 4; kt++)
            ldm_x4(a[4 * kt], a[4 * kt + 1], a[4 * kt + 2], a[4 * kt + 3],
                   aB + (uint32_t)(((gx + 2 * kt) ^ lr) << 4));
        const uint32_t cOff = (uint32_t)(ch * 64 * 128);
#pragma unroll
        for (int ks = 0; ks < 4; ks++) {
            uint32_t b[8];
            ldm_x4(b[0], b[1], b[2], b[3], bBase0 + cOff + ks * 2048);
            ldm_x4(b[4], b[5], b[6], b[7], bBase1 + cOff + ks * 2048);
            mma_bf16(acc[0][0], acc[0][1], acc[0][2], acc[0][3],
                     a[4 * ks], a[4 * ks + 1], a[4 * ks + 2], a[4 * ks + 3], b[0], b[1]);
            mma_bf16(acc[1][0], acc[1][1], acc[1][2], acc[1][3],
                     a[4 * ks], a[4 * ks + 1], a[4 * ks + 2], a[4 * ks + 3], b[2], b[3]);
            mma_bf16(acc[2][0], acc[2][1], acc[2][2], acc[2][3],
                     a[4 * ks], a[4 * ks + 1], a[4 * ks + 2], a[4 * ks + 3], b[4], b[5]);
            mma_bf16(acc[3][0], acc[3][1], acc[3][2], acc[3][3],
                     a[4 * ks], a[4 * ks + 1], a[4 * ks + 2], a[4 * ks + 3], b[6], b[7]);
        }
        if (ch < CHUNKS - 1) {
            XPROC(ch + 1, (ch + 1) & 1);
            if (ch < CHUNKS - 2) XLDG(ch + 2);
            __syncthreads();
        }
    }
    __syncthreads();   // GEMM done; WTB/XB pools now reusable

    // ---- build stage-2 arrays (overlay) ----
    float* zR = (float*)(smem + OFF_ZR);
    float* v1S = (float*)(smem + OFF_V1);
    float* qmS = (float*)(smem + OFF_QM);
    float* s2T = (float*)(smem + OFF_S2T);
    float* na2T = (float*)(smem + OFF_NA2T);
    float* compS = (float*)(smem + OFF_COMP);
    float* klzS = (float*)(smem + OFF_KLZ);
    float* Msm = (float*)(smem + OFF_M);

    for (int i = tid; i < ROWS * 32; i += THREADS) {
        const int r = i >> 5, zp = i & 31;
        const int gi = (rowbase + r) * ZD + 2 * zp;
        float2 qm2 = *(const float2*)(qmu + gi);
        float2 ql2 = *(const float2*)(qls + gi);
        float2 ep2 = *(const float2*)(eps + gi);
        float qs0 = expf(ql2.x), qs1 = expf(ql2.y);
        const int rb = r * RSTR + 2 * zp;
        *(float2*)(zR + rb) = make_float2(fmaf(qs0, ep2.x, qm2.x),
                                          fmaf(qs1, ep2.y, qm2.y));
        *(float2*)(v1S + rb) = make_float2(fmaf(qs0, qs0, qm2.x * qm2.x),
                                           fmaf(qs1, qs1, qm2.y * qm2.y));
        *(float2*)(qmS + rb) = qm2;
    }
    {
        const uint4* s1 = (const uint4*)g_s2T;
        const uint4* s2 = (const uint4*)g_na2T;
        uint4* d1 = (uint4*)s2T;
        uint4* d2 = (uint4*)na2T;
        for (int i = tid; i < (ZD * KK) / 4; i += THREADS) {
            d1[i] = s1[i];
            d2[i] = s2[i];
        }
    }
    __syncthreads();

    // ---- cross term: z . G (fragments) ----
    float zG = 0.f;
    {
        const int dr0 = mrow + (lane >> 2), dr1 = dr0 + 8;
        const int dc = 32 * nh + 2 * (lane & 3);
#pragma unroll
        for (int nt = 0; nt < 4; nt++) {
            float2 z0 = *(const float2*)(zR + dr0 * RSTR + dc + 8 * nt);
            float2 z1 = *(const float2*)(zR + dr1 * RSTR + dc + 8 * nt);
            zG = fmaf(acc[nt][0], z0.x, zG);
            zG = fmaf(acc[nt][1], z0.y, zG);
            zG = fmaf(acc[nt][2], z1.x, zG);
            zG = fmaf(acc[nt][3], z1.y, zG);
        }
    }
    float pxq = (sx0 + sx1) - 2.f * zG;

    // ================= Stage 2a: quadratics + z M z, 2r x 8k ==========
    {
        const int tx = tid & 7, ty = tid >> 3;
        const int kb = 8 * tx, r0 = 2 * ty;
        ull accC[2][4], accK[2][4], accM[2][4];
#pragma unroll
        for (int r = 0; r < 2; r++)
#pragma unroll
            for (int k = 0; k < 4; k++) {
                accC[r][k] = 0ull; accK[r][k] = 0ull; accM[r][k] = 0ull;
            }
        const float* s2p = s2T + kb;
        const float* nap = na2T + kb;
        const float* Mp = Msm + kb;
        const int rb0 = r0 * RSTR, rb1 = rb0 + RSTR;
#pragma unroll 2
        for (int z = 0; z < ZD; z += 2) {
            ulonglong2 sA0 = *(const ulonglong2*)(s2p + z * KK);
            ulonglong2 sB0 = *(const ulonglong2*)(s2p + z * KK + 4);
            ulonglong2 nA0 = *(const ulonglong2*)(nap + z * KK);
            ulonglong2 nB0 = *(const ulonglong2*)(nap + z * KK + 4);
            ulonglong2 mA0 = *(const ulonglong2*)(Mp + z * ZD);
            ulonglong2 mB0 = *(const ulonglong2*)(Mp + z * ZD + 4);
            ulonglong2 sA1 = *(const ulonglong2*)(s2p + (z + 1) * KK);
            ulonglong2 sB1 = *(const ulonglong2*)(s2p + (z + 1) * KK + 4);
            ulonglong2 nA1 = *(const ulonglong2*)(nap + (z + 1) * KK);
            ulonglong2 nB1 = *(const ulonglong2*)(nap + (z + 1) * KK + 4);
            ulonglong2 mA1 = *(const ulonglong2*)(Mp + (z + 1) * ZD);
            ulonglong2 mB1 = *(const ulonglong2*)(Mp + (z + 1) * ZD + 4);
#pragma unroll
            for (int r = 0; r < 2; r++) {
                const int rb = (r ? rb1 : rb0) + z;
                float2 zf = *(const float2*)(zR + rb);
                float2 vf = *(const float2*)(v1S + rb);
                float2 qf = *(const float2*)(qmS + rb);
                ull zd = dup2(zf.x), vd = dup2(vf.x), qd = dup2(qf.x);
                ull t;
                t = fma2o(sA0.x, zd, nA0.x); accC[r][0] = fma2o(t, zd, accC[r][0]);
                t = fma2o(sA0.y, zd, nA0.y); accC[r][1] = fma2o(t, zd, accC[r][1]);
                t = fma2o(sB0.x, zd, nB0.x); accC[r][2] = fma2o(t, zd, accC[r][2]);
                t = fma2o(sB0.y, zd, nB0.y); accC[r][3] = fma2o(t, zd, accC[r][3]);
                accK[r][0] = fma2o(sA0.x, vd, accK[r][0]);
                accK[r][0] = fma2o(nA0.x, qd, accK[r][0]);
                accK[r][1] = fma2o(sA0.y, vd, accK[r][1]);
                accK[r][1] = fma2o(nA0.y, qd, accK[r][1]);
                accK[r][2] = fma2o(sB0.x, vd, accK[r][2]);
                accK[r][2] = fma2o(nB0.x, qd, accK[r][2]);
                accK[r][3] = fma2o(sB0.y, vd, accK[r][3]);
                accK[r][3] = fma2o(nB0.y, qd, accK[r][3]);
                accM[r][0] = fma2o(mA0.x, zd, accM[r][0]);
                accM[r][1] = fma2o(mA0.y, zd, accM[r][1]);
                accM[r][2] = fma2o(mB0.x, zd, accM[r][2]);
                accM[r][3] = fma2o(mB0.y, zd, accM[r][3]);
                zd = dup2(zf.y); vd = dup2(vf.y); qd = dup2(qf.y);
                t = fma2o(sA1.x, zd, nA1.x); accC[r][0] = fma2o(t, zd, accC[r][0]);
                t = fma2o(sA1.y, zd, nA1.y); accC[r][1] = fma2o(t, zd, accC[r][1]);
                t = fma2o(sB1.x, zd, nB1.x); accC[r][2] = fma2o(t, zd, accC[r][2]);
                t = fma2o(sB1.y, zd, nB1.y); accC[r][3] = fma2o(t, zd, accC[r][3]);
                accK[r][0] = fma2o(sA1.x, vd, accK[r][0]);
                accK[r][0] = fma2o(nA1.x, qd, accK[r][0]);
                accK[r][1] = fma2o(sA1.y, vd, accK[r][1]);
                accK[r][1] = fma2o(nA1.y, qd, accK[r][1]);
                accK[r][2] = fma2o(sB1.x, vd, accK[r][2]);
                accK[r][2] = fma2o(nB1.x, qd, accK[r][2]);
                accK[r][3] = fma2o(sB1.y, vd, accK[r][3]);
                accK[r][3] = fma2o(nB1.y, qd, accK[r][3]);
                accM[r][0] = fma2o(mA1.x, zd, accM[r][0]);
                accM[r][1] = fma2o(mA1.y, zd, accM[r][1]);
                accM[r][2] = fma2o(mB1.x, zd, accM[r][2]);
                accM[r][3] = fma2o(mB1.y, zd, accM[r][3]);
            }
        }
        float cc[8], ck[8];
        *(float4*)cc = *(const float4*)(g_cc2 + kb);
        *(float4*)(cc + 4) = *(const float4*)(g_cc2 + kb + 4);
        *(float4*)ck = *(const float4*)(g_ck2 + kb);
        *(float4*)(ck + 4) = *(const float4*)(g_ck2 + kb + 4);
#pragma unroll
        for (int r = 0; r < 2; r++) {
#pragma unroll
            for (int k = 0; k < 4; k++) {
                float lo, hi;
                unpack2(accC[r][k], lo, hi);
                *(float2*)(compS + (r0 + r) * KK + kb + 2 * k) =
                    make_float2(fmaf(-0.5f, lo, cc[2 * k]), fmaf(-0.5f, hi, cc[2 * k + 1]));
                unpack2(accK[r][k], lo, hi);
                *(float2*)(klzS + (r0 + r) * KK + kb + 2 * k) =
                    make_float2(fmaf(0.5f, lo, ck[2 * k]), fmaf(0.5f, hi, ck[2 * k + 1]));
                unpack2(accM[r][k], lo, hi);
                float2 zz = *(const float2*)(zR + (r0 + r) * RSTR + kb + 2 * k);
                pxq = fmaf(lo, zz.x, pxq);
                pxq = fmaf(hi, zz.y, pxq);
            }
        }
    }
    __syncthreads();

    // ================= Stage 2b: softmax / KL (warp per row) =========
    float kl_acc = 0.f;
    for (int rr = 0; rr < 8; rr++) {
        const int r = wid + 16 * rr;
        const int grow = rowbase + r;
        float c0 = compS[r * KK + lane];
        float c1 = compS[r * KK + lane + 32];
        float k0 = klzS[r * KK + lane];
        float k1 = klzS[r * KK + lane + 32];
        float lp0 = logf(pi[grow * KK + lane]);
        float lp1 = logf(pi[grow * KK + lane + 32]);
        float q0 = qls[grow * ZD + lane];
        float q1 = qls[grow * ZD + lane + 32];

        float qsum = q0 + q1;
#pragma unroll
        for (int o = 16; o; o >>= 1) qsum += __shfl_xor_sync(~0u, qsum, o);
        float p0 = c0 + lp0, p1 = c1 + lp1;
        float m = fmaxf(p0, p1);
#pragma unroll
        for (int o = 16; o; o >>= 1) m = fmaxf(m, __shfl_xor_sync(~0u, m, o));
        float e0 = expf(p0 - m), e1 = expf(p1 - m);
        float es = e0 + e1;
#pragma unroll
        for (int o = 16; o; o >>= 1) es += __shfl_xor_sync(~0u, es, o);
        float lse = m + logf(es);
        float inv = 1.f / es;
        float pr0 = e0 * inv, pr1 = e1 * inv;
        float contrib = pr0 * (c0 - lse) + pr1 * (c1 - lse)
                      + pr0 * (k0 - qsum - 32.f) + pr1 * (k1 - qsum - 32.f);
#pragma unroll
        for (int o = 16; o; o >>= 1) contrib += __shfl_xor_sync(~0u, contrib, o);
        if (lane == 0) kl_acc += contrib;
    }

    // ---- deterministic block + grid reduction (fixed-point atomics) ----
    float pxw = pxq;
#pragma unroll
    for (int o = 16; o; o >>= 1) pxw += __shfl_xor_sync(~0u, pxw, o);
    if (lane == 0) { red[wid] = pxw; red[16 + wid] = kl_acc; }
    __syncthreads();
    if (tid == 0) {
        float sp = 0.f, sk = 0.f;
#pragma unroll
        for (int w = 0; w < 16; w++) { sp += red[w]; sk += red[16 + w]; }
        const double part = (double)(-0.5f * sp - sk);
        const long long q = llrint(part * FIXSCALE);
        atomicAdd(&g_acc, (ull)q);
        __threadfence();
        const unsigned t = atomicAdd(&g_cnt, 1u);
        if (t == NBLK - 1) {
            const long long tot = (long long)atomicAdd(&g_acc, 0ull);
            out[0] = (float)((double)tot / FIXSCALE / 16384.0
                             - 0.5 * LOG2PI * (double)XD);
            g_cnt = 0u;
            g_acc = 0ull;
        }
    }
}

extern "C" void kernel_launch(void* const* d_in, const int* in_sizes, int n_in,
                              void* d_out, int out_size) {
    (void)in_sizes; (void)n_in; (void)out_size;
    const float* x    = (const float*)d_in[0];
    const float* pi   = (const float*)d_in[1];
    const float* qmu  = (const float*)d_in[2];
    const float* qls  = (const float*)d_in[3];
    const float* eps  = (const float*)d_in[4];
    const float* pmu  = (const float*)d_in[5];
    const float* pls  = (const float*)d_in[6];
    const float* W    = (const float*)d_in[7];
    const float* bdec = (const float*)d_in[8];

    cudaFuncSetAttribute(main_kernel, cudaFuncAttributeMaxDynamicSharedMemorySize,
                         SMEM_BYTES);
    prep_kernel<<<31, 256>>>(W, pmu, pls);
    main_kernel<<<NBLK, THREADS, SMEM_BYTES>>>(x, pi, qmu, qls, eps, bdec,
                                               (float*)d_out);
}